// round 2
// baseline (speedup 1.0000x reference)
#include <cuda_runtime.h>
#include <math.h>

#define NN   500
#define DEG  16
#define BB   8
#define TT   12
#define HH   64
#define FF   32
#define EE   (NN*DEG)      // 8000
#define BT   (BB*TT)       // 96
#define M1C  16
#define M2C  2
#define DIN  (2*FF+1)      // 65
#define DOUT (2*HH*HH)     // 8192

// Scratch (static device arrays: allocation-free per harness rules)
__device__ float g_c[EE*2];                 // per-edge (c0,c1)
__device__ float g_X[(size_t)NN*6*BT*HH];   // [n][m][bt][h], 73.7 MB

// ---------------------------------------------------------------------------
// K1: per-edge hypernetwork  feat[65] -> sigmoid(16) -> sigmoid(2)
// ---------------------------------------------------------------------------
__global__ void k1_edge_mlp(const float* __restrict__ feature,
                            const float* __restrict__ dist,
                            const float* __restrict__ W1,
                            const float* __restrict__ b1,
                            const float* __restrict__ W2,
                            const float* __restrict__ b2,
                            const int*   __restrict__ src,
                            const int*   __restrict__ dst) {
    __shared__ float w1s[DIN*M1C];
    __shared__ float b1s[M1C];
    __shared__ float w2s[M1C*M2C];
    __shared__ float b2s[M2C];
    int tid = threadIdx.x;
    for (int i = tid; i < DIN*M1C; i += blockDim.x) w1s[i] = W1[i];
    if (tid < M1C)      b1s[tid] = b1[tid];
    if (tid < M1C*M2C)  w2s[tid] = W2[tid];
    if (tid < M2C)      b2s[tid] = b2[tid];
    __syncthreads();

    int e = blockIdx.x * blockDim.x + tid;
    if (e >= EE) return;
    int s = src[e], d = dst[e];
    const float* fs = feature + s*FF;
    const float* fd = feature + d*FF;

    float h1[M1C];
    #pragma unroll
    for (int m = 0; m < M1C; m++) h1[m] = b1s[m];
    #pragma unroll 4
    for (int i = 0; i < FF; i++) {
        float fi = __ldg(fs + i);
        #pragma unroll
        for (int m = 0; m < M1C; m++) h1[m] = fmaf(fi, w1s[i*M1C + m], h1[m]);
    }
    #pragma unroll 4
    for (int i = 0; i < FF; i++) {
        float fi = __ldg(fd + i);
        #pragma unroll
        for (int m = 0; m < M1C; m++) h1[m] = fmaf(fi, w1s[(FF+i)*M1C + m], h1[m]);
    }
    {
        float fi = __ldg(dist + e);
        #pragma unroll
        for (int m = 0; m < M1C; m++) h1[m] = fmaf(fi, w1s[(2*FF)*M1C + m], h1[m]);
    }
    #pragma unroll
    for (int m = 0; m < M1C; m++) h1[m] = 1.0f / (1.0f + __expf(-h1[m]));

    float c0 = b2s[0], c1 = b2s[1];
    #pragma unroll
    for (int m = 0; m < M1C; m++) {
        c0 = fmaf(h1[m], w2s[m*M2C + 0], c0);
        c1 = fmaf(h1[m], w2s[m*M2C + 1], c1);
    }
    c0 = 1.0f / (1.0f + __expf(-c0));
    c1 = 1.0f / (1.0f + __expf(-c1));
    g_c[e*2 + 0] = c0;
    g_c[e*2 + 1] = c1;
}

// ---------------------------------------------------------------------------
// K2: per-node projections  X[n,m] = s[n] ([96,64]) @ W_m ([64,64])
//   m=0: W3 row0 upper, m=1: W3 row1 upper, m=2: b3 upper,
//   m=3: W3 row0 lower, m=4: W3 row1 lower, m=5: b3 lower
// grid = N*6, block = 256 (tx = h, ty = row group)
// ---------------------------------------------------------------------------
__global__ void __launch_bounds__(256) k2_precompute(
        const float* __restrict__ state,
        const float* __restrict__ W3,
        const float* __restrict__ b3) {
    int n = blockIdx.x / 6;
    int m = blockIdx.x % 6;
    __shared__ float s_sm[BT*HH];   // 24 KB
    __shared__ float w_sm[HH*HH];   // 16 KB
    int tid = threadIdx.x;

    // load s[n] (node-major view of state[B,T,N,H]) : coalesced 256B rows
    for (int idx = tid; idx < BT*HH; idx += 256) {
        int bt = idx >> 6, h = idx & 63;
        s_sm[idx] = state[((size_t)bt*NN + n)*HH + h];
    }
    // load W_m
    {
        int r = m % 3;
        const float* wp = (r == 0) ? W3 : (r == 1) ? (W3 + DOUT) : b3;
        int base = (m < 3) ? 0 : HH*HH;   // lower half starts at element 4096
        for (int idx = tid; idx < HH*HH; idx += 256)
            w_sm[idx] = wp[base + idx];
    }
    __syncthreads();

    int h  = tid & 63;
    int ty = tid >> 6;           // 0..3
    float wcol[HH];
    #pragma unroll
    for (int k = 0; k < HH; k++) wcol[k] = w_sm[k*HH + h];

    float* outp = g_X + ((size_t)(n*6 + m))*BT*HH;
    #pragma unroll 2
    for (int rr = 0; rr < BT/4; rr++) {
        int row = ty + 4*rr;
        const float* sr = s_sm + row*HH;
        float acc = 0.f;
        #pragma unroll
        for (int k = 0; k < HH; k++) acc = fmaf(sr[k], wcol[k], acc);
        outp[row*HH + h] = acc;
    }
}

// ---------------------------------------------------------------------------
// K3: per-(node, bt-tile) combine + segment softmax + aggregate
// grid = N*6 (6 bt-tiles of 16), block = 256: tid -> (lbt = tid/16, h4 = tid%16)
// Each thread owns one float4 of (bt, h) output.
// ---------------------------------------------------------------------------
__global__ void __launch_bounds__(256) k3_combine(
        const float* __restrict__ state,
        const float* __restrict__ gate,
        const int*   __restrict__ src,
        const int*   __restrict__ dst,
        float*       __restrict__ out) {
    int n    = blockIdx.x / 6;
    int tile = blockIdx.x % 6;

    __shared__ float c0s[DEG], c1s[DEG];
    __shared__ int   srcs[DEG];
    __shared__ int   dstn_s;
    int tid = threadIdx.x;
    if (tid < DEG) {
        int e = n*DEG + tid;
        srcs[tid] = src[e];
        c0s[tid]  = g_c[e*2 + 0];
        c1s[tid]  = g_c[e*2 + 1];
        if (tid == 0) dstn_s = dst[n*DEG];
    }
    __syncthreads();

    int dstn = dstn_s;
    int h4   = (tid & 15) * 4;
    int bt   = tile*16 + (tid >> 4);

    // dst-side projections (shared across all 16 edges of this node)
    size_t yb = ((size_t)(dstn*6 + 3))*BT*HH + (size_t)bt*HH + h4;
    float4 y0 = *(const float4*)(g_X + yb);
    float4 y1 = *(const float4*)(g_X + yb + (size_t)BT*HH);
    float4 y2 = *(const float4*)(g_X + yb + (size_t)2*BT*HH);

    float4 alph[DEG];
    float4 amax = make_float4(-1e30f, -1e30f, -1e30f, -1e30f);

    #pragma unroll
    for (int j = 0; j < DEG; j++) {
        int sj = srcs[j];
        size_t xb = ((size_t)(sj*6))*BT*HH + (size_t)bt*HH + h4;
        float4 x0 = *(const float4*)(g_X + xb);
        float4 x1 = *(const float4*)(g_X + xb + (size_t)BT*HH);
        float4 x2 = *(const float4*)(g_X + xb + (size_t)2*BT*HH);
        float c0 = c0s[j], c1 = c1s[j];
        float4 a;
        a.x = fmaf(c0, x0.x + y0.x, fmaf(c1, x1.x + y1.x, x2.x + y2.x));
        a.y = fmaf(c0, x0.y + y0.y, fmaf(c1, x1.y + y1.y, x2.y + y2.y));
        a.z = fmaf(c0, x0.z + y0.z, fmaf(c1, x1.z + y1.z, x2.z + y2.z));
        a.w = fmaf(c0, x0.w + y0.w, fmaf(c1, x1.w + y1.w, x2.w + y2.w));
        // leaky_relu(0.01)
        a.x = (a.x > 0.f) ? a.x : 0.01f*a.x;
        a.y = (a.y > 0.f) ? a.y : 0.01f*a.y;
        a.z = (a.z > 0.f) ? a.z : 0.01f*a.z;
        a.w = (a.w > 0.f) ? a.w : 0.01f*a.w;
        alph[j] = a;
        amax.x = fmaxf(amax.x, a.x);
        amax.y = fmaxf(amax.y, a.y);
        amax.z = fmaxf(amax.z, a.z);
        amax.w = fmaxf(amax.w, a.w);
    }

    float4 num = make_float4(0.f, 0.f, 0.f, 0.f);
    float4 den = make_float4(0.f, 0.f, 0.f, 0.f);
    #pragma unroll
    for (int j = 0; j < DEG; j++) {
        float4 e4;
        e4.x = __expf(alph[j].x - amax.x);
        e4.y = __expf(alph[j].y - amax.y);
        e4.z = __expf(alph[j].z - amax.z);
        e4.w = __expf(alph[j].w - amax.w);
        den.x += e4.x; den.y += e4.y; den.z += e4.z; den.w += e4.w;
        float4 s4 = *(const float4*)(state + ((size_t)bt*NN + srcs[j])*HH + h4);
        num.x = fmaf(e4.x, s4.x, num.x);
        num.y = fmaf(e4.y, s4.y, num.y);
        num.z = fmaf(e4.z, s4.z, num.z);
        num.w = fmaf(e4.w, s4.w, num.w);
    }

    float sg = 1.0f / (1.0f + __expf(-gate[0]));
    float4 o;
    o.x = fmaxf(num.x / den.x, 0.f) * sg;
    o.y = fmaxf(num.y / den.y, 0.f) * sg;
    o.z = fmaxf(num.z / den.z, 0.f) * sg;
    o.w = fmaxf(num.w / den.w, 0.f) * sg;
    *(float4*)(out + ((size_t)bt*NN + n)*HH + h4) = o;
}

// ---------------------------------------------------------------------------
extern "C" void kernel_launch(void* const* d_in, const int* in_sizes, int n_in,
                              void* d_out, int out_size) {
    const float* state   = (const float*)d_in[0];
    const float* feature = (const float*)d_in[1];
    const float* dist    = (const float*)d_in[2];
    const float* W1      = (const float*)d_in[3];
    const float* b1      = (const float*)d_in[4];
    const float* W2      = (const float*)d_in[5];
    const float* b2      = (const float*)d_in[6];
    const float* W3      = (const float*)d_in[7];
    const float* b3      = (const float*)d_in[8];
    const float* gate    = (const float*)d_in[9];
    const int*   src     = (const int*)d_in[10];
    const int*   dst     = (const int*)d_in[11];
    float* out = (float*)d_out;

    k1_edge_mlp<<<(EE + 255)/256, 256>>>(feature, dist, W1, b1, W2, b2, src, dst);
    k2_precompute<<<NN*6, 256>>>(state, W3, b3);
    k3_combine<<<NN*6, 256>>>(state, gate, src, dst, out);
}

// round 3
// speedup vs baseline: 2.2251x; 2.2251x over previous
#include <cuda_runtime.h>
#include <math.h>

#define NN   500
#define DEG  16
#define BB   8
#define TT   12
#define HH   64
#define FF   32
#define EE   (NN*DEG)      // 8000
#define BT   (BB*TT)       // 96
#define M1C  16
#define M2C  2
#define DIN  (2*FF+1)      // 65
#define DOUT (2*HH*HH)     // 8192
#define PLANE (BT*HH)      // 6144

// Scratch (static device arrays: allocation-free per harness rules)
__device__ float g_c[EE*2];                 // per-edge (c0,c1)
__device__ float g_X[(size_t)NN*6*PLANE];   // [n][m][bt][h], 73.7 MB

typedef unsigned long long ull;

// ---- packed f32x2 helpers (Blackwell; ptxas never auto-fuses these) -------
__device__ __forceinline__ ull pk2(float lo, float hi) {
    ull r;
    asm("mov.b64 %0, {%1, %2};" : "=l"(r) : "r"(__float_as_uint(lo)), "r"(__float_as_uint(hi)));
    return r;
}
__device__ __forceinline__ ull dup2(float x) {
    ull r;
    asm("mov.b64 %0, {%1, %1};" : "=l"(r) : "r"(__float_as_uint(x)));
    return r;
}
__device__ __forceinline__ void ffma2(ull& d, ull a, ull b) {
    asm("fma.rn.f32x2 %0, %1, %2, %3;" : "=l"(d) : "l"(a), "l"(b), "l"(d));
}
__device__ __forceinline__ void unpk2(ull v, float& lo, float& hi) {
    unsigned ulo, uhi;
    asm("mov.b64 {%0, %1}, %2;" : "=r"(ulo), "=r"(uhi) : "l"(v));
    lo = __uint_as_float(ulo); hi = __uint_as_float(uhi);
}

// ---------------------------------------------------------------------------
// K1: per-edge hypernetwork  feat[65] -> sigmoid(16) -> sigmoid(2)
// 64-thread blocks -> 125 blocks spread across SMs
// ---------------------------------------------------------------------------
__global__ void __launch_bounds__(64) k1_edge_mlp(
        const float* __restrict__ feature,
        const float* __restrict__ dist,
        const float* __restrict__ W1,
        const float* __restrict__ b1,
        const float* __restrict__ W2,
        const float* __restrict__ b2,
        const int*   __restrict__ src,
        const int*   __restrict__ dst) {
    __shared__ float w1s[DIN*M1C];
    __shared__ float b1s[M1C];
    __shared__ float w2s[M1C*M2C];
    __shared__ float b2s[M2C];
    int tid = threadIdx.x;
    for (int i = tid; i < DIN*M1C; i += 64) w1s[i] = W1[i];
    if (tid < M1C)      b1s[tid] = b1[tid];
    if (tid < M1C*M2C)  w2s[tid] = W2[tid];
    if (tid < M2C)      b2s[tid] = b2[tid];
    __syncthreads();

    int e = blockIdx.x * 64 + tid;
    if (e >= EE) return;
    int s = src[e], d = dst[e];
    const float* fs = feature + s*FF;
    const float* fd = feature + d*FF;

    float h1[M1C];
    #pragma unroll
    for (int m = 0; m < M1C; m++) h1[m] = b1s[m];
    #pragma unroll 4
    for (int i = 0; i < FF; i++) {
        float fi = __ldg(fs + i);
        #pragma unroll
        for (int m = 0; m < M1C; m++) h1[m] = fmaf(fi, w1s[i*M1C + m], h1[m]);
    }
    #pragma unroll 4
    for (int i = 0; i < FF; i++) {
        float fi = __ldg(fd + i);
        #pragma unroll
        for (int m = 0; m < M1C; m++) h1[m] = fmaf(fi, w1s[(FF+i)*M1C + m], h1[m]);
    }
    {
        float fi = __ldg(dist + e);
        #pragma unroll
        for (int m = 0; m < M1C; m++) h1[m] = fmaf(fi, w1s[(2*FF)*M1C + m], h1[m]);
    }
    #pragma unroll
    for (int m = 0; m < M1C; m++) h1[m] = 1.0f / (1.0f + __expf(-h1[m]));

    float c0 = b2s[0], c1 = b2s[1];
    #pragma unroll
    for (int m = 0; m < M1C; m++) {
        c0 = fmaf(h1[m], w2s[m*M2C + 0], c0);
        c1 = fmaf(h1[m], w2s[m*M2C + 1], c1);
    }
    g_c[e*2 + 0] = 1.0f / (1.0f + __expf(-c0));
    g_c[e*2 + 1] = 1.0f / (1.0f + __expf(-c1));
}

// ---------------------------------------------------------------------------
// K2: per-node projections  X[n,m] = s[n] ([96,64]) @ W_m ([64,64])
// Register-tiled, packed FFMA2: thread tile = 6 rows x 4 cols (2 f32x2 pairs)
// grid = N*6, block = 256: tidx = tid&15 -> col group, tidy = tid>>4 -> rows
// ---------------------------------------------------------------------------
#define SPITCH 68   // padded s row stride (floats), multiple of 4, avoids bank repeat

__global__ void __launch_bounds__(256) k2_precompute(
        const float* __restrict__ state,
        const float* __restrict__ W3,
        const float* __restrict__ b3) {
    int n = blockIdx.x / 6;
    int m = blockIdx.x % 6;
    __shared__ float s_sm[BT*SPITCH];   // 26.1 KB
    __shared__ float w_sm[HH*HH];       // 16 KB
    int tid = threadIdx.x;

    for (int idx = tid; idx < BT*HH; idx += 256) {
        int bt = idx >> 6, h = idx & 63;
        s_sm[bt*SPITCH + h] = state[((size_t)bt*NN + n)*HH + h];
    }
    {
        int r = m % 3;
        const float* wp = (r == 0) ? W3 : (r == 1) ? (W3 + DOUT) : b3;
        int base = (m < 3) ? 0 : HH*HH;
        for (int idx = tid; idx < HH*HH; idx += 256)
            w_sm[idx] = wp[base + idx];
    }
    __syncthreads();

    int c  = (tid & 15) * 4;    // output cols c..c+3
    int ty = tid >> 4;          // 0..15 ; rows ty, ty+16, ..., ty+80

    ull acc[6][2];
    #pragma unroll
    for (int r = 0; r < 6; r++) { acc[r][0] = 0ull; acc[r][1] = 0ull; }

    #pragma unroll 4
    for (int k4 = 0; k4 < 16; k4++) {
        float4 sv[6];
        #pragma unroll
        for (int r = 0; r < 6; r++)
            sv[r] = *(const float4*)&s_sm[(ty + 16*r)*SPITCH + k4*4];
        #pragma unroll
        for (int kk = 0; kk < 4; kk++) {
            int k = k4*4 + kk;
            float4 wv = *(const float4*)&w_sm[k*HH + c];
            ull w01 = pk2(wv.x, wv.y);
            ull w23 = pk2(wv.z, wv.w);
            #pragma unroll
            for (int r = 0; r < 6; r++) {
                float sval = (kk == 0) ? sv[r].x : (kk == 1) ? sv[r].y
                           : (kk == 2) ? sv[r].z : sv[r].w;
                ull sd = dup2(sval);
                ffma2(acc[r][0], w01, sd);
                ffma2(acc[r][1], w23, sd);
            }
        }
    }

    float* outp = g_X + (size_t)(n*6 + m)*PLANE;
    #pragma unroll
    for (int r = 0; r < 6; r++) {
        int row = ty + 16*r;
        float4 o;
        unpk2(acc[r][0], o.x, o.y);
        unpk2(acc[r][1], o.z, o.w);
        *(float4*)(outp + row*HH + c) = o;
    }
}

// ---------------------------------------------------------------------------
// K3: single-pass combine + softmax (no max-subtraction; |alpha| << 88) +
// aggregate. grid = N*6 bt-tiles, block = 256: tid -> (bt row, h-float4)
// ---------------------------------------------------------------------------
__global__ void __launch_bounds__(256) k3_combine(
        const float* __restrict__ state,
        const float* __restrict__ gate,
        const int*   __restrict__ src,
        const int*   __restrict__ dst,
        float*       __restrict__ out) {
    int n    = blockIdx.x / 6;
    int tile = blockIdx.x % 6;

    __shared__ float c0s[DEG], c1s[DEG];
    __shared__ int   srcs[DEG];
    __shared__ int   dstn_s;
    int tid = threadIdx.x;
    if (tid < DEG) {
        int e = n*DEG + tid;
        srcs[tid] = src[e];
        c0s[tid]  = g_c[e*2 + 0];
        c1s[tid]  = g_c[e*2 + 1];
        if (tid == 0) dstn_s = dst[n*DEG];
    }
    __syncthreads();

    int dstn = dstn_s;
    int h4   = (tid & 15) * 4;
    int bt   = tile*16 + (tid >> 4);

    // dst-side (lower) projections: shared across all 16 edges
    const float* yp = g_X + (size_t)(dstn*6 + 3)*PLANE + (size_t)bt*HH + h4;
    float4 y0 = *(const float4*)(yp);
    float4 y1 = *(const float4*)(yp + PLANE);
    float4 y2 = *(const float4*)(yp + 2*PLANE);

    float4 num = make_float4(0.f, 0.f, 0.f, 0.f);
    float4 den = make_float4(0.f, 0.f, 0.f, 0.f);

    #pragma unroll
    for (int j = 0; j < DEG; j++) {
        int sj = srcs[j];
        const float* xp = g_X + (size_t)(sj*6)*PLANE + (size_t)bt*HH + h4;
        float4 x0 = *(const float4*)(xp);
        float4 x1 = *(const float4*)(xp + PLANE);
        float4 x2 = *(const float4*)(xp + 2*PLANE);
        float4 s4 = *(const float4*)(state + ((size_t)bt*NN + sj)*HH + h4);
        float c0 = c0s[j], c1 = c1s[j];

        float4 a;
        a.x = fmaf(c0, x0.x + y0.x, fmaf(c1, x1.x + y1.x, x2.x + y2.x));
        a.y = fmaf(c0, x0.y + y0.y, fmaf(c1, x1.y + y1.y, x2.y + y2.y));
        a.z = fmaf(c0, x0.z + y0.z, fmaf(c1, x1.z + y1.z, x2.z + y2.z));
        a.w = fmaf(c0, x0.w + y0.w, fmaf(c1, x1.w + y1.w, x2.w + y2.w));
        // leaky_relu(0.01): for a<0, 0.01a > a, so fmax works on both sides
        a.x = fmaxf(a.x, 0.01f*a.x);
        a.y = fmaxf(a.y, 0.01f*a.y);
        a.z = fmaxf(a.z, 0.01f*a.z);
        a.w = fmaxf(a.w, 0.01f*a.w);

        float4 p;
        p.x = __expf(a.x); p.y = __expf(a.y);
        p.z = __expf(a.z); p.w = __expf(a.w);
        den.x += p.x; den.y += p.y; den.z += p.z; den.w += p.w;
        num.x = fmaf(p.x, s4.x, num.x);
        num.y = fmaf(p.y, s4.y, num.y);
        num.z = fmaf(p.z, s4.z, num.z);
        num.w = fmaf(p.w, s4.w, num.w);
    }

    float sg = 1.0f / (1.0f + __expf(-gate[0]));
    float4 o;
    o.x = fmaxf(num.x / den.x, 0.f) * sg;
    o.y = fmaxf(num.y / den.y, 0.f) * sg;
    o.z = fmaxf(num.z / den.z, 0.f) * sg;
    o.w = fmaxf(num.w / den.w, 0.f) * sg;
    *(float4*)(out + ((size_t)bt*NN + n)*HH + h4) = o;
}

// ---------------------------------------------------------------------------
extern "C" void kernel_launch(void* const* d_in, const int* in_sizes, int n_in,
                              void* d_out, int out_size) {
    const float* state   = (const float*)d_in[0];
    const float* feature = (const float*)d_in[1];
    const float* dist    = (const float*)d_in[2];
    const float* W1      = (const float*)d_in[3];
    const float* b1      = (const float*)d_in[4];
    const float* W2      = (const float*)d_in[5];
    const float* b2      = (const float*)d_in[6];
    const float* W3      = (const float*)d_in[7];
    const float* b3      = (const float*)d_in[8];
    const float* gate    = (const float*)d_in[9];
    const int*   src     = (const int*)d_in[10];
    const int*   dst     = (const int*)d_in[11];
    float* out = (float*)d_out;

    k1_edge_mlp<<<(EE + 63)/64, 64>>>(feature, dist, W1, b1, W2, b2, src, dst);
    k2_precompute<<<NN*6, 256>>>(state, W3, b3);
    k3_combine<<<NN*6, 256>>>(state, gate, src, dst, out);
}

// round 4
// speedup vs baseline: 2.9845x; 1.3413x over previous
#include <cuda_runtime.h>
#include <math.h>

#define NN   500
#define DEG  16
#define BB   8
#define TT   12
#define HH   64
#define FF   32
#define EE   (NN*DEG)      // 8000
#define BT   (BB*TT)       // 96
#define M1C  16
#define M2C  2
#define DIN  (2*FF+1)      // 65
#define DOUT (2*HH*HH)     // 8192
#define PLANE (BT*HH)      // 6144
#define SPITCH 68

// Static scratch (allocation-free)
__device__ float g_u[NN*M1C];                // feat@W1_top
__device__ float g_v[NN*M1C];                // feat@W1_bot
__device__ int   g_bias_nz;                  // b3 != 0 anywhere?
__device__ float g_c[EE*2];                  // per-edge (c0,c1)
__device__ float g_A[(size_t)NN*PLANE*2];    // src-side planes interleaved (x0,x1)
__device__ float g_B[(size_t)NN*PLANE*2];    // dst-side planes interleaved (y0,y1)
__device__ float g_Az[(size_t)NN*PLANE];     // src bias plane (only if bias_nz)
__device__ float g_Bz[(size_t)NN*PLANE];     // dst bias plane

typedef unsigned long long ull;

__device__ __forceinline__ ull pk2(float lo, float hi) {
    ull r;
    asm("mov.b64 %0, {%1, %2};" : "=l"(r) : "r"(__float_as_uint(lo)), "r"(__float_as_uint(hi)));
    return r;
}
__device__ __forceinline__ ull dup2(float x) {
    ull r;
    asm("mov.b64 %0, {%1, %1};" : "=l"(r) : "r"(__float_as_uint(x)));
    return r;
}
__device__ __forceinline__ void ffma2(ull& d, ull a, ull b) {
    asm("fma.rn.f32x2 %0, %1, %2, %3;" : "=l"(d) : "l"(a), "l"(b), "l"(d));
}
__device__ __forceinline__ void unpk2(ull v, float& lo, float& hi) {
    unsigned ulo, uhi;
    asm("mov.b64 {%0, %1}, %2;" : "=r"(ulo), "=r"(uhi) : "l"(v));
    lo = __uint_as_float(ulo); hi = __uint_as_float(uhi);
}
__device__ __forceinline__ float sigmoidf_(float x) { return 1.0f / (1.0f + __expf(-x)); }

// ---------------------------------------------------------------------------
// kf: u/v node tables + bias-zero flag. grid=64, block=256.
// ---------------------------------------------------------------------------
__global__ void __launch_bounds__(256) kf_prep(
        const float* __restrict__ feature,
        const float* __restrict__ W1,
        const float* __restrict__ b3) {
    int bid = blockIdx.x, tid = threadIdx.x;
    if (bid == 63) {
        int nz = 0;
        for (int i = tid; i < DOUT; i += 256) nz |= (b3[i] != 0.0f);
        nz = __syncthreads_or(nz);
        if (tid == 0) g_bias_nz = nz;
        return;
    }
    int gid = bid * 256 + tid;        // 0..16127 covers 1000 rows x 16
    int row = gid >> 4;
    if (row >= 2*NN) return;
    int m = gid & 15;
    int n = row >> 1, half = row & 1;
    const float* f = feature + n*FF;
    const float* w = W1 + half*FF*M1C + m;
    float acc = 0.f;
    #pragma unroll
    for (int i = 0; i < FF; i++) acc = fmaf(__ldg(f + i), __ldg(w + i*M1C), acc);
    (half ? g_v : g_u)[n*M1C + m] = acc;
}

// ---------------------------------------------------------------------------
// K2: per-node projections, 2 blocks/node (side 0: upper/src, side 1: lower/dst)
// Each block: load s[n] once, loop over 2 (or 3 if bias) W matrices, FFMA2 GEMM.
// Side-0 threads 0-15 also compute the 16 edge (c0,c1) from u/v tables.
// ---------------------------------------------------------------------------
__global__ void __launch_bounds__(256) k2_precompute(
        const float* __restrict__ state,
        const float* __restrict__ W3,
        const float* __restrict__ b3,
        const float* __restrict__ dist,
        const float* __restrict__ W1,
        const float* __restrict__ b1,
        const float* __restrict__ W2,
        const float* __restrict__ b2,
        const int*   __restrict__ src,
        const int*   __restrict__ dst) {
    int bid  = blockIdx.x;
    int n    = bid >> 1;
    int side = bid & 1;
    __shared__ float s_sm[BT*SPITCH];
    __shared__ float w_sm[HH*HH];
    int tid = threadIdx.x;

    for (int idx = tid; idx < BT*HH; idx += 256) {
        int bt = idx >> 6, h = idx & 63;
        s_sm[bt*SPITCH + h] = state[((size_t)bt*NN + n)*HH + h];
    }
    int bias_nz = g_bias_nz;

    // inline edge hypernetwork (side 0 only, 16 threads)
    if (side == 0 && tid < DEG) {
        int e = n*DEG + tid;
        int s = __ldg(src + e), d = __ldg(dst + e);
        float de = __ldg(dist + e);
        const float* up = g_u + s*M1C;
        const float* vp = g_v + d*M1C;
        float c0 = __ldg(b2 + 0), c1 = __ldg(b2 + 1);
        #pragma unroll
        for (int m = 0; m < M1C; m++) {
            float z = up[m] + vp[m] + de * __ldg(W1 + 2*FF*M1C + m) + __ldg(b1 + m);
            float h1 = sigmoidf_(z);
            c0 = fmaf(h1, __ldg(W2 + m*M2C + 0), c0);
            c1 = fmaf(h1, __ldg(W2 + m*M2C + 1), c1);
        }
        g_c[e*2 + 0] = sigmoidf_(c0);
        g_c[e*2 + 1] = sigmoidf_(c1);
    }

    int c4 = (tid & 15) * 4;
    int ty = tid >> 4;
    float o0[6][4];
    int nm = bias_nz ? 3 : 2;

    for (int mi = 0; mi < nm; mi++) {
        __syncthreads();
        {
            const float* wp = (mi == 0) ? W3 : (mi == 1) ? (W3 + DOUT) : b3;
            int base = side ? HH*HH : 0;
            for (int idx = tid; idx < HH*HH; idx += 256)
                w_sm[idx] = wp[base + idx];
        }
        __syncthreads();

        ull acc[6][2];
        #pragma unroll
        for (int r = 0; r < 6; r++) { acc[r][0] = 0ull; acc[r][1] = 0ull; }

        #pragma unroll 4
        for (int k4 = 0; k4 < 16; k4++) {
            float4 sv[6];
            #pragma unroll
            for (int r = 0; r < 6; r++)
                sv[r] = *(const float4*)&s_sm[(ty + 16*r)*SPITCH + k4*4];
            #pragma unroll
            for (int kk = 0; kk < 4; kk++) {
                int k = k4*4 + kk;
                float4 wv = *(const float4*)&w_sm[k*HH + c4];
                ull w01 = pk2(wv.x, wv.y);
                ull w23 = pk2(wv.z, wv.w);
                #pragma unroll
                for (int r = 0; r < 6; r++) {
                    float sval = (kk == 0) ? sv[r].x : (kk == 1) ? sv[r].y
                               : (kk == 2) ? sv[r].z : sv[r].w;
                    ull sd = dup2(sval);
                    ffma2(acc[r][0], w01, sd);
                    ffma2(acc[r][1], w23, sd);
                }
            }
        }

        if (mi == 0) {
            #pragma unroll
            for (int r = 0; r < 6; r++) {
                unpk2(acc[r][0], o0[r][0], o0[r][1]);
                unpk2(acc[r][1], o0[r][2], o0[r][3]);
            }
        } else if (mi == 1) {
            float* outp = (side ? g_B : g_A) + (size_t)n*PLANE*2;
            #pragma unroll
            for (int r = 0; r < 6; r++) {
                int row = ty + 16*r;
                float m1v[4];
                unpk2(acc[r][0], m1v[0], m1v[1]);
                unpk2(acc[r][1], m1v[2], m1v[3]);
                size_t base = ((size_t)row*HH + c4) * 2;
                *(float4*)(outp + base)     = make_float4(o0[r][0], m1v[0], o0[r][1], m1v[1]);
                *(float4*)(outp + base + 4) = make_float4(o0[r][2], m1v[2], o0[r][3], m1v[3]);
            }
        } else {
            float* outp = (side ? g_Bz : g_Az) + (size_t)n*PLANE;
            #pragma unroll
            for (int r = 0; r < 6; r++) {
                int row = ty + 16*r;
                float zv[4];
                unpk2(acc[r][0], zv[0], zv[1]);
                unpk2(acc[r][1], zv[2], zv[3]);
                *(float4*)(outp + row*HH + c4) = make_float4(zv[0], zv[1], zv[2], zv[3]);
            }
        }
    }
}

// ---------------------------------------------------------------------------
// K3: combine + single-pass softmax + aggregate. grid = N*6 bt-tiles.
// ---------------------------------------------------------------------------
__global__ void __launch_bounds__(256) k3_combine(
        const float* __restrict__ state,
        const float* __restrict__ gate,
        const int*   __restrict__ src,
        const int*   __restrict__ dst,
        float*       __restrict__ out) {
    int n    = blockIdx.x / 6;
    int tile = blockIdx.x % 6;

    __shared__ float c0s[DEG], c1s[DEG];
    __shared__ int   srcs[DEG];
    __shared__ int   dstn_s;
    int tid = threadIdx.x;
    if (tid < DEG) {
        int e = n*DEG + tid;
        srcs[tid] = src[e];
        c0s[tid]  = g_c[e*2 + 0];
        c1s[tid]  = g_c[e*2 + 1];
        if (tid == 0) dstn_s = dst[n*DEG];
    }
    int bias_nz = g_bias_nz;
    __syncthreads();

    int dstn = dstn_s;
    int h4   = (tid & 15) * 4;
    int bt   = tile*16 + (tid >> 4);

    size_t eoff = (size_t)bt*HH + h4;
    const float* yp = g_B + ((size_t)dstn*PLANE + eoff)*2;
    float4 ya = *(const float4*)(yp);       // (y0[0],y1[0],y0[1],y1[1])
    float4 yb = *(const float4*)(yp + 4);   // (y0[2],y1[2],y0[3],y1[3])

    float4 num = make_float4(0.f, 0.f, 0.f, 0.f);
    float4 den = make_float4(0.f, 0.f, 0.f, 0.f);

    if (!bias_nz) {
        #pragma unroll
        for (int j = 0; j < DEG; j++) {
            int sj = srcs[j];
            const float* xp = g_A + ((size_t)sj*PLANE + eoff)*2;
            float4 xa = *(const float4*)(xp);
            float4 xb = *(const float4*)(xp + 4);
            float4 s4 = *(const float4*)(state + ((size_t)bt*NN + sj)*HH + h4);
            float c0 = c0s[j], c1 = c1s[j];
            float4 a;
            a.x = fmaf(c0, xa.x + ya.x, c1 * (xa.y + ya.y));
            a.y = fmaf(c0, xa.z + ya.z, c1 * (xa.w + ya.w));
            a.z = fmaf(c0, xb.x + yb.x, c1 * (xb.y + yb.y));
            a.w = fmaf(c0, xb.z + yb.z, c1 * (xb.w + yb.w));
            a.x = fmaxf(a.x, 0.01f*a.x);
            a.y = fmaxf(a.y, 0.01f*a.y);
            a.z = fmaxf(a.z, 0.01f*a.z);
            a.w = fmaxf(a.w, 0.01f*a.w);
            float4 p;
            p.x = __expf(a.x); p.y = __expf(a.y);
            p.z = __expf(a.z); p.w = __expf(a.w);
            den.x += p.x; den.y += p.y; den.z += p.z; den.w += p.w;
            num.x = fmaf(p.x, s4.x, num.x);
            num.y = fmaf(p.y, s4.y, num.y);
            num.z = fmaf(p.z, s4.z, num.z);
            num.w = fmaf(p.w, s4.w, num.w);
        }
    } else {
        float4 y2 = *(const float4*)(g_Bz + (size_t)dstn*PLANE + eoff);
        #pragma unroll
        for (int j = 0; j < DEG; j++) {
            int sj = srcs[j];
            const float* xp = g_A + ((size_t)sj*PLANE + eoff)*2;
            float4 xa = *(const float4*)(xp);
            float4 xb = *(const float4*)(xp + 4);
            float4 x2 = *(const float4*)(g_Az + (size_t)sj*PLANE + eoff);
            float4 s4 = *(const float4*)(state + ((size_t)bt*NN + sj)*HH + h4);
            float c0 = c0s[j], c1 = c1s[j];
            float4 a;
            a.x = fmaf(c0, xa.x + ya.x, fmaf(c1, xa.y + ya.y, x2.x + y2.x));
            a.y = fmaf(c0, xa.z + ya.z, fmaf(c1, xa.w + ya.w, x2.y + y2.y));
            a.z = fmaf(c0, xb.x + yb.x, fmaf(c1, xb.y + yb.y, x2.z + y2.z));
            a.w = fmaf(c0, xb.z + yb.z, fmaf(c1, xb.w + yb.w, x2.w + y2.w));
            a.x = fmaxf(a.x, 0.01f*a.x);
            a.y = fmaxf(a.y, 0.01f*a.y);
            a.z = fmaxf(a.z, 0.01f*a.z);
            a.w = fmaxf(a.w, 0.01f*a.w);
            float4 p;
            p.x = __expf(a.x); p.y = __expf(a.y);
            p.z = __expf(a.z); p.w = __expf(a.w);
            den.x += p.x; den.y += p.y; den.z += p.z; den.w += p.w;
            num.x = fmaf(p.x, s4.x, num.x);
            num.y = fmaf(p.y, s4.y, num.y);
            num.z = fmaf(p.z, s4.z, num.z);
            num.w = fmaf(p.w, s4.w, num.w);
        }
    }

    float sg = 1.0f / (1.0f + __expf(-gate[0]));
    float4 o;
    o.x = fmaxf(num.x / den.x, 0.f) * sg;
    o.y = fmaxf(num.y / den.y, 0.f) * sg;
    o.z = fmaxf(num.z / den.z, 0.f) * sg;
    o.w = fmaxf(num.w / den.w, 0.f) * sg;
    *(float4*)(out + ((size_t)bt*NN + n)*HH + h4) = o;
}

// ---------------------------------------------------------------------------
extern "C" void kernel_launch(void* const* d_in, const int* in_sizes, int n_in,
                              void* d_out, int out_size) {
    const float* state   = (const float*)d_in[0];
    const float* feature = (const float*)d_in[1];
    const float* dist    = (const float*)d_in[2];
    const float* W1      = (const float*)d_in[3];
    const float* b1      = (const float*)d_in[4];
    const float* W2      = (const float*)d_in[5];
    const float* b2      = (const float*)d_in[6];
    const float* W3      = (const float*)d_in[7];
    const float* b3      = (const float*)d_in[8];
    const float* gate    = (const float*)d_in[9];
    const int*   src     = (const int*)d_in[10];
    const int*   dst     = (const int*)d_in[11];
    float* out = (float*)d_out;

    kf_prep<<<64, 256>>>(feature, W1, b3);
    k2_precompute<<<NN*2, 256>>>(state, W3, b3, dist, W1, b1, W2, b2, src, dst);
    k3_combine<<<NN*6, 256>>>(state, gate, src, dst, out);
}